// round 1
// baseline (speedup 1.0000x reference)
#include <cuda_runtime.h>
#include <math.h>

#define B_   8
#define N_   3137
#define C_   768
#define H_   8
#define c_   96
#define IMG  56
#define QKVC 2304
#define M_   (B_*N_)      // 25096

#define NCHUNK 16
#define CHUNK  197
#define SPLITK 4
#define KVCHUNK 785

// ---------------- scratch (device globals: allocation-guard compliant) ------
__device__ float g_qkv[(size_t)M_*QKVC];          // 231 MB  q|k|v per token
__device__ float g_attn[(size_t)M_*C_];           // 77 MB   pre-proj
__device__ float g_kvpart[(size_t)SPLITK*B_*H_*c_*c_];
__device__ float g_kv[B_*H_*c_*c_];
__device__ float g_pmax[NCHUNK*B_*C_];
__device__ float g_psum[NCHUNK*B_*C_];
__device__ float g_smax[B_*C_];
__device__ float g_sinv[B_*C_];

// ---------------- generic SGEMM: C[m,n] = sum_k A[m,k]*B[n,k] + bias[n] -----
__global__ __launch_bounds__(256) void sgemm_tn(
    const float* __restrict__ A, const float* __restrict__ Bm,
    const float* __restrict__ bias, float* __restrict__ C,
    int M, int N, int K)
{
    __shared__ float As[16][128];
    __shared__ float Bs[16][128];
    int tid = threadIdx.x;
    int bm = blockIdx.y * 128, bn = blockIdx.x * 128;
    int tx = tid & 15, ty = tid >> 4;

    float acc[8][8];
#pragma unroll
    for (int i = 0; i < 8; i++)
#pragma unroll
        for (int j = 0; j < 8; j++) acc[i][j] = 0.f;

    int lrow = tid >> 2;            // 0..63
    int lk4  = (tid & 3) * 4;       // 0,4,8,12

    const float* Aptr = A + (size_t)(bm + lrow) * K + lk4;
    const float* Bptr = Bm + (size_t)(bn + lrow) * K + lk4;
    bool av0 = (bm + lrow) < M;
    bool av1 = (bm + lrow + 64) < M;

    for (int k0 = 0; k0 < K; k0 += 16) {
        float4 a0 = av0 ? *(const float4*)(Aptr + k0) : make_float4(0.f,0.f,0.f,0.f);
        float4 a1 = av1 ? *(const float4*)(Aptr + (size_t)64 * K + k0) : make_float4(0.f,0.f,0.f,0.f);
        float4 b0 = *(const float4*)(Bptr + k0);
        float4 b1 = *(const float4*)(Bptr + (size_t)64 * K + k0);
        __syncthreads();
        As[lk4+0][lrow] = a0.x; As[lk4+1][lrow] = a0.y; As[lk4+2][lrow] = a0.z; As[lk4+3][lrow] = a0.w;
        As[lk4+0][lrow+64] = a1.x; As[lk4+1][lrow+64] = a1.y; As[lk4+2][lrow+64] = a1.z; As[lk4+3][lrow+64] = a1.w;
        Bs[lk4+0][lrow] = b0.x; Bs[lk4+1][lrow] = b0.y; Bs[lk4+2][lrow] = b0.z; Bs[lk4+3][lrow] = b0.w;
        Bs[lk4+0][lrow+64] = b1.x; Bs[lk4+1][lrow+64] = b1.y; Bs[lk4+2][lrow+64] = b1.z; Bs[lk4+3][lrow+64] = b1.w;
        __syncthreads();
#pragma unroll
        for (int k = 0; k < 16; k++) {
            float4 x0 = *(const float4*)&As[k][ty*8];
            float4 x1 = *(const float4*)&As[k][ty*8+4];
            float4 y0 = *(const float4*)&Bs[k][tx*8];
            float4 y1 = *(const float4*)&Bs[k][tx*8+4];
            float a[8] = {x0.x,x0.y,x0.z,x0.w,x1.x,x1.y,x1.z,x1.w};
            float b[8] = {y0.x,y0.y,y0.z,y0.w,y1.x,y1.y,y1.z,y1.w};
#pragma unroll
            for (int i = 0; i < 8; i++)
#pragma unroll
                for (int j = 0; j < 8; j++) acc[i][j] += a[i]*b[j];
        }
    }

    float bv[8];
#pragma unroll
    for (int j = 0; j < 8; j++) bv[j] = bias[bn + tx*8 + j];
#pragma unroll
    for (int i = 0; i < 8; i++) {
        int m = bm + ty*8 + i;
        if (m < M) {
            float* crow = C + (size_t)m * N + bn + tx*8;
            float4 o0, o1;
            o0.x = acc[i][0]+bv[0]; o0.y = acc[i][1]+bv[1]; o0.z = acc[i][2]+bv[2]; o0.w = acc[i][3]+bv[3];
            o1.x = acc[i][4]+bv[4]; o1.y = acc[i][5]+bv[5]; o1.z = acc[i][6]+bv[6]; o1.w = acc[i][7]+bv[7];
            *(float4*)(crow)   = o0;
            *(float4*)(crow+4) = o1;
        }
    }
}

// ---------------- softmax column stats over N (chunked, online) -------------
__global__ void k_stats_partial()
{
    int b = blockIdx.x, jg = blockIdx.y, ch = blockIdx.z;
    int j = jg*256 + threadIdx.x;         // 0..767  (h*96+c)
    int n0 = ch*CHUNK;
    int n1 = min(n0 + CHUNK, N_);
    const float* base = g_qkv + ((size_t)b*N_ + n0)*QKVC + C_ + j;
    float m = -1e30f, s = 0.f;
    for (int n = n0; n < n1; n++, base += QKVC) {
        float v = *base;
        if (v > m) { s = s*__expf(m - v) + 1.f; m = v; }
        else       { s += __expf(v - m); }
    }
    int col = b*C_ + j;
    g_pmax[ch*(B_*C_) + col] = m;
    g_psum[ch*(B_*C_) + col] = s;
}

__global__ void k_stats_combine()
{
    int col = blockIdx.x*256 + threadIdx.x;
    if (col >= B_*C_) return;
    float m = -1e30f;
#pragma unroll
    for (int ch = 0; ch < NCHUNK; ch++) m = fmaxf(m, g_pmax[ch*(B_*C_)+col]);
    float s = 0.f;
#pragma unroll
    for (int ch = 0; ch < NCHUNK; ch++) s += g_psum[ch*(B_*C_)+col]*__expf(g_pmax[ch*(B_*C_)+col]-m);
    g_smax[col] = m;
    g_sinv[col] = 1.f/s;
}

// ---------------- kv[b,h,c,d] = sum_n softmax(k)[n,c] * v[n,d]  (split-K) ---
__global__ __launch_bounds__(256) void k_kv()
{
    int bh = blockIdx.x; int b = bh >> 3, h = bh & 7;
    int sk = blockIdx.y;
    int n0 = sk*KVCHUNK;
    int n1 = min(n0 + KVCHUNK, N_);

    __shared__ float Kt[16][96], Vt[16][96];
    __shared__ float smax[96], sinv[96];
    int tid = threadIdx.x;
    if (tid < 96) {
        smax[tid] = g_smax[b*C_ + h*c_ + tid];
        sinv[tid] = g_sinv[b*C_ + h*c_ + tid];
    }
    int tx = tid & 15, ty = tid >> 4;
    float acc[6][6];
#pragma unroll
    for (int i = 0; i < 6; i++)
#pragma unroll
        for (int j = 0; j < 6; j++) acc[i][j] = 0.f;

    for (int nt = n0; nt < n1; nt += 16) {
        __syncthreads();
        for (int i = tid; i < 16*96; i += 256) {
            int r = i/96, jj = i - r*96;
            int n = nt + r;
            float kv = 0.f, vv = 0.f;
            if (n < n1) {
                const float* row = g_qkv + ((size_t)(b*N_ + n))*QKVC + h*c_;
                kv = __expf(row[C_ + jj] - smax[jj]) * sinv[jj];
                vv = row[2*C_ + jj];
            }
            Kt[r][jj] = kv; Vt[r][jj] = vv;
        }
        __syncthreads();
#pragma unroll
        for (int r = 0; r < 16; r++) {
            float2 k0 = *(const float2*)&Kt[r][ty*6];
            float2 k1 = *(const float2*)&Kt[r][ty*6+2];
            float2 k2 = *(const float2*)&Kt[r][ty*6+4];
            float2 v0 = *(const float2*)&Vt[r][tx*6];
            float2 v1 = *(const float2*)&Vt[r][tx*6+2];
            float2 v2 = *(const float2*)&Vt[r][tx*6+4];
            float ka[6] = {k0.x,k0.y,k1.x,k1.y,k2.x,k2.y};
            float vb[6] = {v0.x,v0.y,v1.x,v1.y,v2.x,v2.y};
#pragma unroll
            for (int i = 0; i < 6; i++)
#pragma unroll
                for (int j = 0; j < 6; j++) acc[i][j] += ka[i]*vb[j];
        }
    }
    float* out = g_kvpart + ((size_t)sk*(B_*H_) + bh)*(c_*c_);
#pragma unroll
    for (int i = 0; i < 6; i++)
#pragma unroll
        for (int j = 0; j < 6; j++)
            out[(ty*6+i)*96 + tx*6 + j] = acc[i][j];
}

__global__ void k_kv_reduce()
{
    int i = blockIdx.x*256 + threadIdx.x;
    if (i >= B_*H_*c_*c_) return;
    float s = 0.f;
#pragma unroll
    for (int sk = 0; sk < SPLITK; sk++) s += g_kvpart[(size_t)sk*(B_*H_*c_*c_) + i];
    g_kv[i] = s;
}

// ---------------- factor_att: g_attn = scale * q @ kv -----------------------
__global__ __launch_bounds__(256) void k_fact()
{
    extern __shared__ float sm[];
    float* kvs = sm;              // [96][96]
    float* qst = sm + 96*96;      // [96][68]  (k-major transposed q tile, padded)

    int bh = blockIdx.x; int b = bh >> 3, h = bh & 7;
    int n0 = blockIdx.y * 64;
    int tid = threadIdx.x;

    for (int i = tid; i < 96*96; i += 256) kvs[i] = g_kv[(size_t)bh*(c_*c_) + i];
    for (int i = tid; i < 64*96; i += 256) {
        int r = i/96, j = i - r*96;
        int n = n0 + r;
        float q = 0.f;
        if (n < N_) q = g_qkv[((size_t)(b*N_+n))*QKVC + h*c_ + j];
        qst[j*68 + r] = q;
    }
    __syncthreads();

    int tx = tid & 15, ty = tid >> 4;
    float acc[4][6];
#pragma unroll
    for (int i = 0; i < 4; i++)
#pragma unroll
        for (int j = 0; j < 6; j++) acc[i][j] = 0.f;

#pragma unroll 4
    for (int k = 0; k < 96; k++) {
        float4 qv = *(const float4*)&qst[k*68 + ty*4];
        float2 b0 = *(const float2*)&kvs[k*96 + tx*6];
        float2 b1 = *(const float2*)&kvs[k*96 + tx*6 + 2];
        float2 b2 = *(const float2*)&kvs[k*96 + tx*6 + 4];
        float qa[4] = {qv.x,qv.y,qv.z,qv.w};
        float bb[6] = {b0.x,b0.y,b1.x,b1.y,b2.x,b2.y};
#pragma unroll
        for (int i = 0; i < 4; i++)
#pragma unroll
            for (int j = 0; j < 6; j++) acc[i][j] += qa[i]*bb[j];
    }

    const float scale = 0.10206207261596577f;  // 96^-0.5
#pragma unroll
    for (int i = 0; i < 4; i++) {
        int n = n0 + ty*4 + i;
        if (n < N_) {
            float* o = g_attn + ((size_t)(b*N_+n))*C_ + h*c_ + tx*6;
            float2 s0 = make_float2(scale*acc[i][0], scale*acc[i][1]);
            float2 s1 = make_float2(scale*acc[i][2], scale*acc[i][3]);
            float2 s2 = make_float2(scale*acc[i][4], scale*acc[i][5]);
            *(float2*)(o)   = s0;
            *(float2*)(o+2) = s1;
            *(float2*)(o+4) = s2;
        }
    }
}

// ---------------- crpe: g_attn += q * (dwconv(v) + bias) --------------------
template <int KSZ>
__global__ __launch_bounds__(256) void k_crpe(const float* __restrict__ w,
                                              const float* __restrict__ bias,
                                              int ch_base)
{
    const int KK = KSZ*KSZ;
    int tile = blockIdx.x;           // 0..48 (7x7 tiles of 8x8)
    int cg   = blockIdx.y;           // channel group (32 ch) within this segment
    int b    = blockIdx.z;
    int ch0  = ch_base + cg*32;
    int ty0  = (tile/7)*8, tx0 = (tile%7)*8;

    __shared__ float wsm[32*49];
    __shared__ float bsm[32];
    __shared__ float patch[196][32];

    int tid = threadIdx.x;
    for (int i = tid; i < 32*KK; i += 256) {
        int chl = i / KK, wi = i - chl*KK;
        wsm[chl*KK + wi] = w[(cg*32 + chl)*KK + wi];
    }
    if (tid < 32) bsm[tid] = bias[cg*32 + tid];

    int lc = tid & 31, lp = tid >> 5;
    for (int p = lp; p < 196; p += 8) {
        int py = p/14 - 3 + ty0, px = p - (p/14)*14 - 3 + tx0;
        float v = 0.f;
        if ((unsigned)py < IMG && (unsigned)px < IMG)
            v = g_qkv[((size_t)(b*N_ + 1 + py*IMG + px))*QKVC + 2*C_ + ch0 + lc];
        patch[p][lc] = v;
    }
    __syncthreads();

    float wr[KK];
#pragma unroll
    for (int i = 0; i < KK; i++) wr[i] = wsm[lc*KK + i];
    float bval = bsm[lc];

    float acc[8];
#pragma unroll
    for (int i = 0; i < 8; i++) acc[i] = 0.f;

    const int pad = KSZ/2, off = 3 - pad;
#pragma unroll
    for (int dy = 0; dy < KSZ; dy++) {
        int prow = (lp + off + dy)*14;
        float r[KSZ + 7];
#pragma unroll
        for (int x = 0; x < KSZ + 7; x++) r[x] = patch[prow + off + x][lc];
#pragma unroll
        for (int ox = 0; ox < 8; ox++)
#pragma unroll
            for (int dx = 0; dx < KSZ; dx++)
                acc[ox] += r[ox+dx]*wr[dy*KSZ+dx];
    }

    int gy = ty0 + lp;
#pragma unroll
    for (int ox = 0; ox < 8; ox++) {
        int gx = tx0 + ox;
        size_t n = (size_t)b*N_ + 1 + gy*IMG + gx;
        float q = g_qkv[n*QKVC + ch0 + lc];
        g_attn[n*C_ + ch0 + lc] += q*(acc[ox] + bval);
    }
}

// ---------------- launch ----------------------------------------------------
extern "C" void kernel_launch(void* const* d_in, const int* in_sizes, int n_in,
                              void* d_out, int out_size)
{
    const float* x       = (const float*)d_in[0];
    const float* qkv_w   = (const float*)d_in[1];
    const float* qkv_b   = (const float*)d_in[2];
    const float* proj_w  = (const float*)d_in[3];
    const float* proj_b  = (const float*)d_in[4];
    const float* conv3_w = (const float*)d_in[5];
    const float* conv3_b = (const float*)d_in[6];
    const float* conv5_w = (const float*)d_in[7];
    const float* conv5_b = (const float*)d_in[8];
    const float* conv7_w = (const float*)d_in[9];
    const float* conv7_b = (const float*)d_in[10];

    float* qkv;  cudaGetSymbolAddress((void**)&qkv,  g_qkv);
    float* attn; cudaGetSymbolAddress((void**)&attn, g_attn);

    // 1) qkv = x @ qkv_w^T + b
    sgemm_tn<<<dim3(QKVC/128, (M_+127)/128), 256>>>(x, qkv_w, qkv_b, qkv, M_, QKVC, C_);

    // 2) softmax column stats over N
    k_stats_partial<<<dim3(B_, 3, NCHUNK), 256>>>();
    k_stats_combine<<<(B_*C_ + 255)/256, 256>>>();

    // 3) kv = k_softmax^T @ v   (split-K + deterministic reduce)
    k_kv<<<dim3(B_*H_, SPLITK), 256>>>();
    k_kv_reduce<<<(B_*H_*c_*c_ + 255)/256, 256>>>();

    // 4) g_attn = scale * q @ kv
    static bool attr_set = false;
    if (!attr_set) {
        cudaFuncSetAttribute(k_fact, cudaFuncAttributeMaxDynamicSharedMemorySize, 64*1024);
        attr_set = true;
    }
    k_fact<<<dim3(B_*H_, (N_+63)/64), 256, (96*96 + 96*68)*sizeof(float)>>>();

    // 5) crpe: g_attn += q * dwconv(v)
    k_crpe<3><<<dim3(49, 6, B_), 256>>>(conv3_w, conv3_b, 0);
    k_crpe<5><<<dim3(49, 9, B_), 256>>>(conv5_w, conv5_b, 192);
    k_crpe<7><<<dim3(49, 9, B_), 256>>>(conv7_w, conv7_b, 480);

    // 6) out = attn @ proj_w^T + proj_b
    sgemm_tn<<<dim3(C_/128, (M_+127)/128), 256>>>(attn, proj_w, proj_b, (float*)d_out, M_, C_, C_);
}

// round 3
// speedup vs baseline: 1.8367x; 1.8367x over previous
#include <cuda_runtime.h>
#include <math.h>
#include <cstdint>

#define B_   8
#define N_   3137
#define C_   768
#define H_   8
#define c_   96
#define IMG  56
#define QKVC 2304
#define M_   (B_*N_)      // 25096

#define NCHUNK 16
#define CHUNK  197
#define SPLITK 4
#define KVCHUNK 785

// ---------------- scratch (device globals: allocation-guard compliant) ------
__device__ float g_qkv[(size_t)M_*QKVC];          // 231 MB  q|k|v per token
__device__ float g_attn[(size_t)M_*C_];           // 77 MB   pre-proj
__device__ float g_kvpart[(size_t)SPLITK*B_*H_*c_*c_];
__device__ float g_kv[B_*H_*c_*c_];
__device__ float g_pmax[NCHUNK*B_*C_];
__device__ float g_psum[NCHUNK*B_*C_];
__device__ float g_smax[B_*C_];
__device__ float g_sinv[B_*C_];

// =====================  tf32 mma.sync GEMM: C = A @ W^T + bias  =============
// Portable sm_80 PTX path (compute_103 virtual target rejects tcgen05).
// BM=128, BN=128, BK=32, 256 threads = 8 warps (2 x 4).
// Each warp: 64x32 output = 4x4 tiles of m16n8k8.

__device__ __forceinline__ uint32_t f2tf(float f){
    uint32_t r; asm("cvt.rna.tf32.f32 %0, %1;" : "=r"(r) : "f"(f)); return r;
}

__device__ __forceinline__ void mma_tf32(float* c, const uint32_t* a, const uint32_t* b){
    asm volatile(
        "mma.sync.aligned.m16n8k8.row.col.f32.tf32.tf32.f32 "
        "{%0,%1,%2,%3}, {%4,%5,%6,%7}, {%8,%9}, {%0,%1,%2,%3};"
        : "+f"(c[0]), "+f"(c[1]), "+f"(c[2]), "+f"(c[3])
        : "r"(a[0]), "r"(a[1]), "r"(a[2]), "r"(a[3]), "r"(b[0]), "r"(b[1]));
}

// smem per buffer: A frag region 4096 floats + B frag region 4096 floats.
// Fragment-contiguous layout:
//  A: word ((kstep*8 + mtile)*32 + lane)*4 + f,  f = khi*2 + hi
//  B: word ((kstep*16 + ntile)*32 + lane)*2 + khi
#define GBUF 8192

__global__ __launch_bounds__(256) void gemm_mma(
    const float* __restrict__ A, const float* __restrict__ W,
    const float* __restrict__ bias, float* __restrict__ C,
    int M, int N, int K)
{
    extern __shared__ float sm[];
    int tid = threadIdx.x, lane = tid & 31, wid = tid >> 5;
    int warp_m = wid & 1, warp_n = wid >> 1;
    int bm = blockIdx.y * 128, bn = blockIdx.x * 128;

    float acc[4][4][4];
#pragma unroll
    for (int i = 0; i < 4; i++)
#pragma unroll
        for (int j = 0; j < 4; j++)
#pragma unroll
            for (int r = 0; r < 4; r++) acc[i][j][r] = 0.f;

    float4 ra[4], rb[4];

    auto ldg = [&](int t){
#pragma unroll
        for (int it = 0; it < 4; it++) {
            int idx = tid + it * 256;          // 0..1023
            int row = idx >> 3, kq = idx & 7;  // row 0..127, float4 col 0..7
            const float* ap = A + (size_t)(bm + row) * K + t * 32 + kq * 4;
            ra[it] = (bm + row < M) ? *(const float4*)ap : make_float4(0.f,0.f,0.f,0.f);
            rb[it] = *(const float4*)(W + (size_t)(bn + row) * K + t * 32 + kq * 4);
        }
    };
    auto sts = [&](int t){
        float* sA = sm + (t % 3) * GBUF;
        float* sB = sA + 4096;
#pragma unroll
        for (int it = 0; it < 4; it++) {
            int idx = tid + it * 256;
            int row = idx >> 3, kq = idx & 7;
            int kstep = kq >> 1, khi = kq & 1;
            // A fragment scatter
            int mtile = row >> 4, r16 = row & 15;
            int g = r16 & 7, hi = r16 >> 3;
            int af = ((kstep * 8 + mtile) * 32 + g * 4) * 4 + khi * 2 + hi;
            sA[af + 0]  = __uint_as_float(f2tf(ra[it].x));
            sA[af + 4]  = __uint_as_float(f2tf(ra[it].y));
            sA[af + 8]  = __uint_as_float(f2tf(ra[it].z));
            sA[af + 12] = __uint_as_float(f2tf(ra[it].w));
            // B fragment scatter
            int ntile = row >> 3, ng = row & 7;
            int bf = ((kstep * 16 + ntile) * 32 + ng * 4) * 2 + khi;
            sB[bf + 0] = __uint_as_float(f2tf(rb[it].x));
            sB[bf + 2] = __uint_as_float(f2tf(rb[it].y));
            sB[bf + 4] = __uint_as_float(f2tf(rb[it].z));
            sB[bf + 6] = __uint_as_float(f2tf(rb[it].w));
        }
    };
    auto domma = [&](int t){
        const float* sA = sm + (t % 3) * GBUF;
        const float* sB = sA + 4096;
#pragma unroll
        for (int ks = 0; ks < 4; ks++) {
            uint4 a[4]; uint2 b[4];
#pragma unroll
            for (int i = 0; i < 4; i++)
                a[i] = *(const uint4*)&sA[((ks * 8 + warp_m * 4 + i) * 32 + lane) * 4];
#pragma unroll
            for (int j = 0; j < 4; j++)
                b[j] = *(const uint2*)&sB[((ks * 16 + warp_n * 4 + j) * 32 + lane) * 2];
#pragma unroll
            for (int i = 0; i < 4; i++)
#pragma unroll
                for (int j = 0; j < 4; j++)
                    mma_tf32(acc[i][j], (const uint32_t*)&a[i], (const uint32_t*)&b[j]);
        }
    };

    const int T = K / 32;
    ldg(0); sts(0);
    ldg(1); sts(1);
    __syncthreads();

    for (int t = 0; t < T; t++) {
        if (t + 2 < T) ldg(t + 2);
        domma(t);
        if (t + 2 < T) sts(t + 2);
        __syncthreads();
    }

    // epilogue
    int g = lane >> 2, tg = lane & 3;
#pragma unroll
    for (int i = 0; i < 4; i++) {
        int row0 = bm + warp_m * 64 + i * 16 + g;
        int row1 = row0 + 8;
#pragma unroll
        for (int j = 0; j < 4; j++) {
            int col = bn + warp_n * 32 + j * 8 + tg * 2;
            float2 bv = *(const float2*)&bias[col];
            if (row0 < M) {
                float2 o = make_float2(acc[i][j][0] + bv.x, acc[i][j][1] + bv.y);
                *(float2*)(C + (size_t)row0 * N + col) = o;
            }
            if (row1 < M) {
                float2 o = make_float2(acc[i][j][2] + bv.x, acc[i][j][3] + bv.y);
                *(float2*)(C + (size_t)row1 * N + col) = o;
            }
        }
    }
}

// ---------------- softmax column stats over N (chunked, online) -------------
__global__ void k_stats_partial()
{
    int b = blockIdx.x, jg = blockIdx.y, ch = blockIdx.z;
    int j = jg*256 + threadIdx.x;         // 0..767  (h*96+c)
    int n0 = ch*CHUNK;
    int n1 = min(n0 + CHUNK, N_);
    const float* base = g_qkv + ((size_t)b*N_ + n0)*QKVC + C_ + j;
    float m = -1e30f, s = 0.f;
    for (int n = n0; n < n1; n++, base += QKVC) {
        float v = *base;
        if (v > m) { s = s*__expf(m - v) + 1.f; m = v; }
        else       { s += __expf(v - m); }
    }
    int col = b*C_ + j;
    g_pmax[ch*(B_*C_) + col] = m;
    g_psum[ch*(B_*C_) + col] = s;
}

__global__ void k_stats_combine()
{
    int col = blockIdx.x*256 + threadIdx.x;
    if (col >= B_*C_) return;
    float m = -1e30f;
#pragma unroll
    for (int ch = 0; ch < NCHUNK; ch++) m = fmaxf(m, g_pmax[ch*(B_*C_)+col]);
    float s = 0.f;
#pragma unroll
    for (int ch = 0; ch < NCHUNK; ch++) s += g_psum[ch*(B_*C_)+col]*__expf(g_pmax[ch*(B_*C_)+col]-m);
    g_smax[col] = m;
    g_sinv[col] = 1.f/s;
}

// ---------------- kv[b,h,c,d] = sum_n softmax(k)[n,c] * v[n,d]  (split-K) ---
__global__ __launch_bounds__(256) void k_kv()
{
    int bh = blockIdx.x; int b = bh >> 3, h = bh & 7;
    int sk = blockIdx.y;
    int n0 = sk*KVCHUNK;
    int n1 = min(n0 + KVCHUNK, N_);

    __shared__ float Kt[16][96], Vt[16][96];
    __shared__ float smax[96], sinv[96];
    int tid = threadIdx.x;
    if (tid < 96) {
        smax[tid] = g_smax[b*C_ + h*c_ + tid];
        sinv[tid] = g_sinv[b*C_ + h*c_ + tid];
    }
    int tx = tid & 15, ty = tid >> 4;
    float acc[6][6];
#pragma unroll
    for (int i = 0; i < 6; i++)
#pragma unroll
        for (int j = 0; j < 6; j++) acc[i][j] = 0.f;

    for (int nt = n0; nt < n1; nt += 16) {
        __syncthreads();
        for (int i = tid; i < 16*96; i += 256) {
            int r = i/96, jj = i - r*96;
            int n = nt + r;
            float kv = 0.f, vv = 0.f;
            if (n < n1) {
                const float* row = g_qkv + ((size_t)(b*N_ + n))*QKVC + h*c_;
                kv = __expf(row[C_ + jj] - smax[jj]) * sinv[jj];
                vv = row[2*C_ + jj];
            }
            Kt[r][jj] = kv; Vt[r][jj] = vv;
        }
        __syncthreads();
#pragma unroll
        for (int r = 0; r < 16; r++) {
            float2 k0 = *(const float2*)&Kt[r][ty*6];
            float2 k1 = *(const float2*)&Kt[r][ty*6+2];
            float2 k2 = *(const float2*)&Kt[r][ty*6+4];
            float2 v0 = *(const float2*)&Vt[r][tx*6];
            float2 v1 = *(const float2*)&Vt[r][tx*6+2];
            float2 v2 = *(const float2*)&Vt[r][tx*6+4];
            float ka[6] = {k0.x,k0.y,k1.x,k1.y,k2.x,k2.y};
            float vb[6] = {v0.x,v0.y,v1.x,v1.y,v2.x,v2.y};
#pragma unroll
            for (int i = 0; i < 6; i++)
#pragma unroll
                for (int j = 0; j < 6; j++) acc[i][j] += ka[i]*vb[j];
        }
    }
    float* out = g_kvpart + ((size_t)sk*(B_*H_) + bh)*(c_*c_);
#pragma unroll
    for (int i = 0; i < 6; i++)
#pragma unroll
        for (int j = 0; j < 6; j++)
            out[(ty*6+i)*96 + tx*6 + j] = acc[i][j];
}

__global__ void k_kv_reduce()
{
    int i = blockIdx.x*256 + threadIdx.x;
    if (i >= B_*H_*c_*c_) return;
    float s = 0.f;
#pragma unroll
    for (int sk = 0; sk < SPLITK; sk++) s += g_kvpart[(size_t)sk*(B_*H_*c_*c_) + i];
    g_kv[i] = s;
}

// ---------------- factor_att: g_attn = scale * q @ kv -----------------------
__global__ __launch_bounds__(256) void k_fact()
{
    extern __shared__ float smf[];
    float* kvs = smf;             // [96][96]
    float* qst = smf + 96*96;     // [96][68]  (k-major transposed q tile, padded)

    int bh = blockIdx.x; int b = bh >> 3, h = bh & 7;
    int n0 = blockIdx.y * 64;
    int tid = threadIdx.x;

    for (int i = tid; i < 96*96; i += 256) kvs[i] = g_kv[(size_t)bh*(c_*c_) + i];
    for (int i = tid; i < 64*96; i += 256) {
        int r = i/96, j = i - r*96;
        int n = n0 + r;
        float q = 0.f;
        if (n < N_) q = g_qkv[((size_t)(b*N_+n))*QKVC + h*c_ + j];
        qst[j*68 + r] = q;
    }
    __syncthreads();

    int tx = tid & 15, ty = tid >> 4;
    float acc[4][6];
#pragma unroll
    for (int i = 0; i < 4; i++)
#pragma unroll
        for (int j = 0; j < 6; j++) acc[i][j] = 0.f;

#pragma unroll 4
    for (int k = 0; k < 96; k++) {
        float4 qv = *(const float4*)&qst[k*68 + ty*4];
        float2 b0 = *(const float2*)&kvs[k*96 + tx*6];
        float2 b1 = *(const float2*)&kvs[k*96 + tx*6 + 2];
        float2 b2 = *(const float2*)&kvs[k*96 + tx*6 + 4];
        float qa[4] = {qv.x,qv.y,qv.z,qv.w};
        float bb[6] = {b0.x,b0.y,b1.x,b1.y,b2.x,b2.y};
#pragma unroll
        for (int i = 0; i < 4; i++)
#pragma unroll
            for (int j = 0; j < 6; j++) acc[i][j] += qa[i]*bb[j];
    }

    const float scale = 0.10206207261596577f;  // 96^-0.5
#pragma unroll
    for (int i = 0; i < 4; i++) {
        int n = n0 + ty*4 + i;
        if (n < N_) {
            float* o = g_attn + ((size_t)(b*N_+n))*C_ + h*c_ + tx*6;
            float2 s0 = make_float2(scale*acc[i][0], scale*acc[i][1]);
            float2 s1 = make_float2(scale*acc[i][2], scale*acc[i][3]);
            float2 s2 = make_float2(scale*acc[i][4], scale*acc[i][5]);
            *(float2*)(o)   = s0;
            *(float2*)(o+2) = s1;
            *(float2*)(o+4) = s2;
        }
    }
}

// ---------------- crpe: g_attn += q * (dwconv(v) + bias) --------------------
template <int KSZ>
__global__ __launch_bounds__(256) void k_crpe(const float* __restrict__ w,
                                              const float* __restrict__ bias,
                                              int ch_base)
{
    const int KK = KSZ*KSZ;
    int tile = blockIdx.x;           // 0..48 (7x7 tiles of 8x8)
    int cg   = blockIdx.y;           // channel group (32 ch) within this segment
    int b    = blockIdx.z;
    int ch0  = ch_base + cg*32;
    int ty0  = (tile/7)*8, tx0 = (tile%7)*8;

    __shared__ float wsm[32*49];
    __shared__ float bsm[32];
    __shared__ float patch[196][32];

    int tid = threadIdx.x;
    for (int i = tid; i < 32*KK; i += 256) {
        int chl = i / KK, wi = i - chl*KK;
        wsm[chl*KK + wi] = w[(cg*32 + chl)*KK + wi];
    }
    if (tid < 32) bsm[tid] = bias[cg*32 + tid];

    int lc = tid & 31, lp = tid >> 5;
    for (int p = lp; p < 196; p += 8) {
        int py = p/14 - 3 + ty0, px = p - (p/14)*14 - 3 + tx0;
        float v = 0.f;
        if ((unsigned)py < IMG && (unsigned)px < IMG)
            v = g_qkv[((size_t)(b*N_ + 1 + py*IMG + px))*QKVC + 2*C_ + ch0 + lc];
        patch[p][lc] = v;
    }
    __syncthreads();

    float wr[KK];
#pragma unroll
    for (int i = 0; i < KK; i++) wr[i] = wsm[lc*KK + i];
    float bval = bsm[lc];

    float acc[8];
#pragma unroll
    for (int i = 0; i < 8; i++) acc[i] = 0.f;

    const int pad = KSZ/2, off = 3 - pad;
#pragma unroll
    for (int dy = 0; dy < KSZ; dy++) {
        int prow = (lp + off + dy)*14;
        float r[KSZ + 7];
#pragma unroll
        for (int x = 0; x < KSZ + 7; x++) r[x] = patch[prow + off + x][lc];
#pragma unroll
        for (int ox = 0; ox < 8; ox++)
#pragma unroll
            for (int dx = 0; dx < KSZ; dx++)
                acc[ox] += r[ox+dx]*wr[dy*KSZ+dx];
    }

    int gy = ty0 + lp;
#pragma unroll
    for (int ox = 0; ox < 8; ox++) {
        int gx = tx0 + ox;
        size_t n = (size_t)b*N_ + 1 + gy*IMG + gx;
        float q = g_qkv[n*QKVC + ch0 + lc];
        g_attn[n*C_ + ch0 + lc] += q*(acc[ox] + bval);
    }
}

// ---------------- launch ----------------------------------------------------
extern "C" void kernel_launch(void* const* d_in, const int* in_sizes, int n_in,
                              void* d_out, int out_size)
{
    const float* x       = (const float*)d_in[0];
    const float* qkv_w   = (const float*)d_in[1];
    const float* qkv_b   = (const float*)d_in[2];
    const float* proj_w  = (const float*)d_in[3];
    const float* proj_b  = (const float*)d_in[4];
    const float* conv3_w = (const float*)d_in[5];
    const float* conv3_b = (const float*)d_in[6];
    const float* conv5_w = (const float*)d_in[7];
    const float* conv5_b = (const float*)d_in[8];
    const float* conv7_w = (const float*)d_in[9];
    const float* conv7_b = (const float*)d_in[10];

    float* qkv;  cudaGetSymbolAddress((void**)&qkv,  g_qkv);
    float* attn; cudaGetSymbolAddress((void**)&attn, g_attn);

    const int GEMM_SMEM = 3 * GBUF * sizeof(float);   // 96 KB

    static bool attr_set = false;
    if (!attr_set) {
        cudaFuncSetAttribute(k_fact, cudaFuncAttributeMaxDynamicSharedMemorySize, 64*1024);
        cudaFuncSetAttribute(gemm_mma, cudaFuncAttributeMaxDynamicSharedMemorySize, GEMM_SMEM);
        attr_set = true;
    }

    // 1) qkv = x @ qkv_w^T + b   (tf32 mma.sync)
    gemm_mma<<<dim3(QKVC/128, (M_+127)/128), 256, GEMM_SMEM>>>(
        x, qkv_w, qkv_b, qkv, M_, QKVC, C_);

    // 2) softmax column stats over N
    k_stats_partial<<<dim3(B_, 3, NCHUNK), 256>>>();
    k_stats_combine<<<(B_*C_ + 255)/256, 256>>>();

    // 3) kv = k_softmax^T @ v   (split-K + deterministic reduce)
    k_kv<<<dim3(B_*H_, SPLITK), 256>>>();
    k_kv_reduce<<<(B_*H_*c_*c_ + 255)/256, 256>>>();

    // 4) g_attn = scale * q @ kv
    k_fact<<<dim3(B_*H_, (N_+63)/64), 256, (96*96 + 96*68)*sizeof(float)>>>();

    // 5) crpe: g_attn += q * dwconv(v)
    k_crpe<3><<<dim3(49, 6, B_), 256>>>(conv3_w, conv3_b, 0);
    k_crpe<5><<<dim3(49, 9, B_), 256>>>(conv5_w, conv5_b, 192);
    k_crpe<7><<<dim3(49, 9, B_), 256>>>(conv7_w, conv7_b, 480);

    // 6) out = attn @ proj_w^T + proj_b   (tf32 mma.sync)
    gemm_mma<<<dim3(C_/128, (M_+127)/128), 256, GEMM_SMEM>>>(
        attn, proj_w, proj_b, (float*)d_out, M_, C_, C_);
}

// round 5
// speedup vs baseline: 2.5965x; 1.4137x over previous
#include <cuda_runtime.h>
#include <math.h>
#include <cstdint>

#define B_   8
#define N_   3137
#define C_   768
#define H_   8
#define c_   96
#define IMG  56
#define QKVC 2304
#define M_   (B_*N_)      // 25096

#define NCHUNK 16
#define CHUNK  197
#define SPLITK 16
#define KVCHUNK 197

// ---------------- scratch (device globals: allocation-guard compliant) ------
__device__ float g_qkv[(size_t)M_*QKVC];          // 231 MB  q|k|v per token
__device__ float g_attn[(size_t)M_*C_];           // 77 MB   pre-proj
__device__ float g_kvpart[(size_t)SPLITK*B_*H_*c_*c_];
__device__ float g_kv[B_*H_*c_*c_];
__device__ float g_pmax[NCHUNK*B_*C_];
__device__ float g_psum[NCHUNK*B_*C_];
__device__ float g_smax[B_*C_];
__device__ float g_sinv[B_*C_];

// =====================  tf32 mma.sync GEMM: C = A @ W^T + bias  =============
// BM=128, BN=256, BK=32, 256 threads = 8 warps (2m x 4n), warp tile 64x64.
// Fragment-contiguous smem with kstep rotation (bank-conflict reduction).

__device__ __forceinline__ uint32_t f2tf(float f){
    uint32_t r; asm("cvt.rna.tf32.f32 %0, %1;" : "=r"(r) : "f"(f)); return r;
}

__device__ __forceinline__ void mma_tf32(float* c, const uint32_t* a, const uint32_t* b){
    asm volatile(
        "mma.sync.aligned.m16n8k8.row.col.f32.tf32.tf32.f32 "
        "{%0,%1,%2,%3}, {%4,%5,%6,%7}, {%8,%9}, {%0,%1,%2,%3};"
        : "+f"(c[0]), "+f"(c[1]), "+f"(c[2]), "+f"(c[3])
        : "r"(a[0]), "r"(a[1]), "r"(a[2]), "r"(a[3]), "r"(b[0]), "r"(b[1]));
}

#define GSTG 12288   // floats per stage: A 4096 + B 8192

__global__ __launch_bounds__(256, 1) void gemm_mma(
    const float* __restrict__ A, const float* __restrict__ W,
    const float* __restrict__ bias, float* __restrict__ C,
    int M, int N, int K)
{
    extern __shared__ float sm[];
    int tid = threadIdx.x, lane = tid & 31, wid = tid >> 5;
    int warp_m = wid & 1, warp_n = wid >> 1;
    int bm = blockIdx.y * 128, bn = blockIdx.x * 256;

    float acc[4][8][4];
#pragma unroll
    for (int i = 0; i < 4; i++)
#pragma unroll
        for (int j = 0; j < 8; j++)
#pragma unroll
            for (int r = 0; r < 4; r++) acc[i][j][r] = 0.f;

    float4 ra[4], rb[8];

    auto ldg = [&](int t){
#pragma unroll
        for (int it = 0; it < 4; it++) {
            int idx = tid + it * 256;          // 0..1023
            int row = idx >> 3, kq = idx & 7;
            const float* ap = A + (size_t)(bm + row) * K + t * 32 + kq * 4;
            ra[it] = (bm + row < M) ? *(const float4*)ap : make_float4(0.f,0.f,0.f,0.f);
        }
#pragma unroll
        for (int it = 0; it < 8; it++) {
            int idx = tid + it * 256;          // 0..2047
            int row = idx >> 3, kq = idx & 7;
            rb[it] = *(const float4*)(W + (size_t)(bn + row) * K + t * 32 + kq * 4);
        }
    };
    auto sts = [&](int t){
        float* sA = sm + (t & 1) * GSTG;
        float* sB = sA + 4096;
#pragma unroll
        for (int it = 0; it < 4; it++) {
            int idx = tid + it * 256;
            int row = idx >> 3, kq = idx & 7;
            int kstep = kq >> 1, khi = kq & 1;
            int mtile = row >> 4, r16 = row & 15;
            int g = r16 & 7, hi = r16 >> 3;
            int base = (kstep * 8 + mtile) * 32;
            float va[4] = {ra[it].x, ra[it].y, ra[it].z, ra[it].w};
#pragma unroll
            for (int j = 0; j < 4; j++) {
                int slot = (g * 4 + j + kstep) & 31;
                sA[(base + slot) * 4 + khi * 2 + hi] = __uint_as_float(f2tf(va[j]));
            }
        }
#pragma unroll
        for (int it = 0; it < 8; it++) {
            int idx = tid + it * 256;
            int row = idx >> 3, kq = idx & 7;
            int kstep = kq >> 1, khi = kq & 1;
            int ntile = row >> 3, ng = row & 7;
            int base = (kstep * 32 + ntile) * 32;
            float vb[4] = {rb[it].x, rb[it].y, rb[it].z, rb[it].w};
#pragma unroll
            for (int j = 0; j < 4; j++) {
                int slot = (ng * 4 + j + kstep) & 31;
                sB[(base + slot) * 2 + khi] = __uint_as_float(f2tf(vb[j]));
            }
        }
    };
    auto domma = [&](int t){
        const float* sA = sm + (t & 1) * GSTG;
        const float* sB = sA + 4096;
#pragma unroll
        for (int ks = 0; ks < 4; ks++) {
            int rlane = (lane + ks) & 31;
            uint4 a[4]; uint2 b[8];
#pragma unroll
            for (int i = 0; i < 4; i++)
                a[i] = *(const uint4*)&sA[((ks * 8 + warp_m * 4 + i) * 32 + rlane) * 4];
#pragma unroll
            for (int j = 0; j < 8; j++)
                b[j] = *(const uint2*)&sB[((ks * 32 + warp_n * 8 + j) * 32 + rlane) * 2];
#pragma unroll
            for (int i = 0; i < 4; i++)
#pragma unroll
                for (int j = 0; j < 8; j++)
                    mma_tf32(acc[i][j], (const uint32_t*)&a[i], (const uint32_t*)&b[j]);
        }
    };

    const int T = K / 32;
    ldg(0); sts(0);
    __syncthreads();

    for (int t = 0; t < T; t++) {
        if (t + 1 < T) ldg(t + 1);
        domma(t);
        if (t + 1 < T) sts(t + 1);
        __syncthreads();
    }

    // epilogue
    int g = lane >> 2, tg = lane & 3;
#pragma unroll
    for (int i = 0; i < 4; i++) {
        int row0 = bm + warp_m * 64 + i * 16 + g;
        int row1 = row0 + 8;
#pragma unroll
        for (int j = 0; j < 8; j++) {
            int col = bn + warp_n * 64 + j * 8 + tg * 2;
            float2 bv = *(const float2*)&bias[col];
            if (row0 < M) {
                float2 o = make_float2(acc[i][j][0] + bv.x, acc[i][j][1] + bv.y);
                *(float2*)(C + (size_t)row0 * N + col) = o;
            }
            if (row1 < M) {
                float2 o = make_float2(acc[i][j][2] + bv.x, acc[i][j][3] + bv.y);
                *(float2*)(C + (size_t)row1 * N + col) = o;
            }
        }
    }
}

// ---------------- softmax column stats over N (chunked, online) -------------
__global__ void k_stats_partial()
{
    int b = blockIdx.x, jg = blockIdx.y, ch = blockIdx.z;
    int j = jg*256 + threadIdx.x;
    int n0 = ch*CHUNK;
    int n1 = min(n0 + CHUNK, N_);
    const float* base = g_qkv + ((size_t)b*N_ + n0)*QKVC + C_ + j;
    float m = -1e30f, s = 0.f;
    for (int n = n0; n < n1; n++, base += QKVC) {
        float v = *base;
        if (v > m) { s = s*__expf(m - v) + 1.f; m = v; }
        else       { s += __expf(v - m); }
    }
    int col = b*C_ + j;
    g_pmax[ch*(B_*C_) + col] = m;
    g_psum[ch*(B_*C_) + col] = s;
}

__global__ void k_stats_combine()
{
    int col = blockIdx.x*256 + threadIdx.x;
    if (col >= B_*C_) return;
    float m = -1e30f;
#pragma unroll
    for (int ch = 0; ch < NCHUNK; ch++) m = fmaxf(m, g_pmax[ch*(B_*C_)+col]);
    float s = 0.f;
#pragma unroll
    for (int ch = 0; ch < NCHUNK; ch++) s += g_psum[ch*(B_*C_)+col]*__expf(g_pmax[ch*(B_*C_)+col]-m);
    g_smax[col] = m;
    g_sinv[col] = 1.f/s;
}

// ---------------- kv[b,h,c,d] = sum_n exp(k[n,c]-max[c]) * v[n,d] -----------
// (sinv applied in reduce).  Double-buffered tiles, 1 barrier per 16 rows.
__global__ __launch_bounds__(256) void k_kv()
{
    int bh = blockIdx.x; int b = bh >> 3, h = bh & 7;
    int sk = blockIdx.y;
    int n0 = sk*KVCHUNK;
    int n1 = min(n0 + KVCHUNK, N_);

    __shared__ float Kb[2][16][96], Vb[2][16][96];
    __shared__ float smax[96];
    int tid = threadIdx.x;
    if (tid < 96) smax[tid] = g_smax[b*C_ + h*c_ + tid];
    __syncthreads();

    int tx = tid & 15, ty = tid >> 4;
    float acc[6][6];
#pragma unroll
    for (int i = 0; i < 6; i++)
#pragma unroll
        for (int j = 0; j < 6; j++) acc[i][j] = 0.f;

    int nt = (n1 - n0 + 15) >> 4;
    float4 r[3];

    auto ldg = [&](int t){
#pragma unroll
        for (int it = 0; it < 3; it++) {
            int idx = tid + it * 256;           // 0..767
            int rr = idx / 48, f = idx % 48;
            int n = n0 + t * 16 + rr;
            float4 v;
            if (n < n1) {
                const float* row = g_qkv + (size_t)(b*N_ + n)*QKVC;
                if (f < 24) v = *(const float4*)(row + C_ + h*c_ + f*4);
                else        v = *(const float4*)(row + 2*C_ + h*c_ + (f-24)*4);
            } else {
                float pad = (f < 24) ? -1e30f : 0.f;   // exp sentinel for K rows
                v = make_float4(pad, pad, pad, pad);
            }
            r[it] = v;
        }
    };
    auto sts = [&](int t){
        int buf = t & 1;
#pragma unroll
        for (int it = 0; it < 3; it++) {
            int idx = tid + it * 256;
            int rr = idx / 48, f = idx % 48;
            float4 v = r[it];
            if (f < 24) {
                int cc = f*4;
                float4 e;
                e.x = __expf(v.x - smax[cc+0]);
                e.y = __expf(v.y - smax[cc+1]);
                e.z = __expf(v.z - smax[cc+2]);
                e.w = __expf(v.w - smax[cc+3]);
                *(float4*)&Kb[buf][rr][cc] = e;
            } else {
                *(float4*)&Vb[buf][rr][(f-24)*4] = v;
            }
        }
    };

    ldg(0); sts(0);
    __syncthreads();

    for (int t = 0; t < nt; t++) {
        if (t + 1 < nt) ldg(t + 1);
        int buf = t & 1;
#pragma unroll
        for (int rr = 0; rr < 16; rr++) {
            float2 k0 = *(const float2*)&Kb[buf][rr][ty*6];
            float2 k1 = *(const float2*)&Kb[buf][rr][ty*6+2];
            float2 k2 = *(const float2*)&Kb[buf][rr][ty*6+4];
            float2 v0 = *(const float2*)&Vb[buf][rr][tx*6];
            float2 v1 = *(const float2*)&Vb[buf][rr][tx*6+2];
            float2 v2 = *(const float2*)&Vb[buf][rr][tx*6+4];
            float ka[6] = {k0.x,k0.y,k1.x,k1.y,k2.x,k2.y};
            float vb[6] = {v0.x,v0.y,v1.x,v1.y,v2.x,v2.y};
#pragma unroll
            for (int i = 0; i < 6; i++)
#pragma unroll
                for (int j = 0; j < 6; j++) acc[i][j] += ka[i]*vb[j];
        }
        if (t + 1 < nt) sts(t + 1);
        __syncthreads();
    }

    float* out = g_kvpart + ((size_t)sk*(B_*H_) + bh)*(c_*c_);
#pragma unroll
    for (int i = 0; i < 6; i++)
#pragma unroll
        for (int j = 0; j < 6; j++)
            out[(ty*6+i)*96 + tx*6 + j] = acc[i][j];
}

__global__ void k_kv_reduce()
{
    int i = blockIdx.x*256 + threadIdx.x;
    if (i >= B_*H_*c_*c_) return;
    int bh = i / (c_*c_);
    int rem = i - bh*(c_*c_);
    int cc = rem / c_;
    int b = bh >> 3, h = bh & 7;
    float s = 0.f;
#pragma unroll
    for (int sk = 0; sk < SPLITK; sk++)
        s += g_kvpart[((size_t)sk*(B_*H_) + bh)*(c_*c_) + rem];
    g_kv[i] = s * g_sinv[b*C_ + h*c_ + cc];
}

// ---------------- factor_att: g_attn = scale * q @ kv -----------------------
// 128-row n-tiles, 8x6 micro-tile.
__global__ __launch_bounds__(256) void k_fact()
{
    extern __shared__ float smf[];
    float* kvs = smf;             // [96][96]
    float* qst = smf + 96*96;     // [96][132]  k-major transposed q tile, padded

    int bh = blockIdx.x; int b = bh >> 3, h = bh & 7;
    int n0 = blockIdx.y * 128;
    int tid = threadIdx.x;

    for (int i = tid; i < 96*96; i += 256) kvs[i] = g_kv[(size_t)bh*(c_*c_) + i];
    for (int i = tid; i < 128*96; i += 256) {
        int rr = i / 96, j = i - rr*96;
        int n = n0 + rr;
        float q = 0.f;
        if (n < N_) q = g_qkv[((size_t)(b*N_+n))*QKVC + h*c_ + j];
        qst[j*132 + rr] = q;
    }
    __syncthreads();

    int tx = tid & 15, ty = tid >> 4;    // ty 0..15 -> 8 rows each
    float acc[8][6];
#pragma unroll
    for (int i = 0; i < 8; i++)
#pragma unroll
        for (int j = 0; j < 6; j++) acc[i][j] = 0.f;

#pragma unroll 2
    for (int k = 0; k < 96; k++) {
        float4 q0 = *(const float4*)&qst[k*132 + ty*8];
        float4 q1 = *(const float4*)&qst[k*132 + ty*8 + 4];
        float2 b0 = *(const float2*)&kvs[k*96 + tx*6];
        float2 b1 = *(const float2*)&kvs[k*96 + tx*6 + 2];
        float2 b2 = *(const float2*)&kvs[k*96 + tx*6 + 4];
        float qa[8] = {q0.x,q0.y,q0.z,q0.w,q1.x,q1.y,q1.z,q1.w};
        float bb[6] = {b0.x,b0.y,b1.x,b1.y,b2.x,b2.y};
#pragma unroll
        for (int i = 0; i < 8; i++)
#pragma unroll
            for (int j = 0; j < 6; j++) acc[i][j] += qa[i]*bb[j];
    }

    const float scale = 0.10206207261596577f;  // 96^-0.5
#pragma unroll
    for (int i = 0; i < 8; i++) {
        int n = n0 + ty*8 + i;
        if (n < N_) {
            float* o = g_attn + ((size_t)(b*N_+n))*C_ + h*c_ + tx*6;
            *(float2*)(o)   = make_float2(scale*acc[i][0], scale*acc[i][1]);
            *(float2*)(o+2) = make_float2(scale*acc[i][2], scale*acc[i][3]);
            *(float2*)(o+4) = make_float2(scale*acc[i][4], scale*acc[i][5]);
        }
    }
}

// ---------------- crpe: g_attn += q * (dwconv(v) + bias) --------------------
template <int KSZ>
__global__ __launch_bounds__(256) void k_crpe(const float* __restrict__ w,
                                              const float* __restrict__ bias,
                                              int ch_base)
{
    const int KK = KSZ*KSZ;
    int tile = blockIdx.x;
    int cg   = blockIdx.y;
    int b    = blockIdx.z;
    int ch0  = ch_base + cg*32;
    int ty0  = (tile/7)*8, tx0 = (tile%7)*8;

    __shared__ float wsm[32*49];
    __shared__ float bsm[32];
    __shared__ float patch[196][32];

    int tid = threadIdx.x;
    for (int i = tid; i < 32*KK; i += 256) {
        int chl = i / KK, wi = i - chl*KK;
        wsm[chl*KK + wi] = w[(cg*32 + chl)*KK + wi];
    }
    if (tid < 32) bsm[tid] = bias[cg*32 + tid];

    int lc = tid & 31, lp = tid >> 5;
    for (int p = lp; p < 196; p += 8) {
        int py = p/14 - 3 + ty0, px = p - (p/14)*14 - 3 + tx0;
        float v = 0.f;
        if ((unsigned)py < IMG && (unsigned)px < IMG)
            v = g_qkv[((size_t)(b*N_ + 1 + py*IMG + px))*QKVC + 2*C_ + ch0 + lc];
        patch[p][lc] = v;
    }
    __syncthreads();

    float wr[KK];
#pragma unroll
    for (int i = 0; i < KK; i++) wr[i] = wsm[lc*KK + i];
    float bval = bsm[lc];

    float acc[8];
#pragma unroll
    for (int i = 0; i < 8; i++) acc[i] = 0.f;

    const int pad = KSZ/2, off = 3 - pad;
#pragma unroll
    for (int dy = 0; dy < KSZ; dy++) {
        int prow = (lp + off + dy)*14;
        float r[KSZ + 7];
#pragma unroll
        for (int x = 0; x < KSZ + 7; x++) r[x] = patch[prow + off + x][lc];
#pragma unroll
        for (int ox = 0; ox < 8; ox++)
#pragma unroll
            for (int dx = 0; dx < KSZ; dx++)
                acc[ox] += r[ox+dx]*wr[dy*KSZ+dx];
    }

    int gy = ty0 + lp;
#pragma unroll
    for (int ox = 0; ox < 8; ox++) {
        int gx = tx0 + ox;
        size_t n = (size_t)b*N_ + 1 + gy*IMG + gx;
        float q = g_qkv[n*QKVC + ch0 + lc];
        g_attn[n*C_ + ch0 + lc] += q*(acc[ox] + bval);
    }
}

// ---------------- launch ----------------------------------------------------
extern "C" void kernel_launch(void* const* d_in, const int* in_sizes, int n_in,
                              void* d_out, int out_size)
{
    const float* x       = (const float*)d_in[0];
    const float* qkv_w   = (const float*)d_in[1];
    const float* qkv_b   = (const float*)d_in[2];
    const float* proj_w  = (const float*)d_in[3];
    const float* proj_b  = (const float*)d_in[4];
    const float* conv3_w = (const float*)d_in[5];
    const float* conv3_b = (const float*)d_in[6];
    const float* conv5_w = (const float*)d_in[7];
    const float* conv5_b = (const float*)d_in[8];
    const float* conv7_w = (const float*)d_in[9];
    const float* conv7_b = (const float*)d_in[10];

    float* qkv;  cudaGetSymbolAddress((void**)&qkv,  g_qkv);
    float* attn; cudaGetSymbolAddress((void**)&attn, g_attn);

    const int GEMM_SMEM = 2 * GSTG * sizeof(float);          // 96 KB
    const int FACT_SMEM = (96*96 + 96*132) * sizeof(float);  // ~85.5 KB

    static bool attr_set = false;
    if (!attr_set) {
        cudaFuncSetAttribute(k_fact, cudaFuncAttributeMaxDynamicSharedMemorySize, FACT_SMEM);
        cudaFuncSetAttribute(gemm_mma, cudaFuncAttributeMaxDynamicSharedMemorySize, GEMM_SMEM);
        attr_set = true;
    }

    // 1) qkv = x @ qkv_w^T + b   (tf32 mma.sync)
    gemm_mma<<<dim3(QKVC/256, (M_+127)/128), 256, GEMM_SMEM>>>(
        x, qkv_w, qkv_b, qkv, M_, QKVC, C_);

    // 2) softmax column stats over N
    k_stats_partial<<<dim3(B_, 3, NCHUNK), 256>>>();
    k_stats_combine<<<(B_*C_ + 255)/256, 256>>>();

    // 3) kv = k_softmax^T @ v   (split-K 16 + deterministic reduce)
    k_kv<<<dim3(B_*H_, SPLITK), 256>>>();
    k_kv_reduce<<<(B_*H_*c_*c_ + 255)/256, 256>>>();

    // 4) g_attn = scale * q @ kv
    k_fact<<<dim3(B_*H_, (N_+127)/128), 256, FACT_SMEM>>>();

    // 5) crpe: g_attn += q * dwconv(v)
    k_crpe<3><<<dim3(49, 6, B_), 256>>>(conv3_w, conv3_b, 0);
    k_crpe<5><<<dim3(49, 9, B_), 256>>>(conv5_w, conv5_b, 192);
    k_crpe<7><<<dim3(49, 9, B_), 256>>>(conv7_w, conv7_b, 480);

    // 6) out = attn @ proj_w^T + proj_b   (tf32 mma.sync)
    gemm_mma<<<dim3(C_/256, (M_+127)/128), 256, GEMM_SMEM>>>(
        attn, proj_w, proj_b, (float*)d_out, M_, C_, C_);
}